// round 5
// baseline (speedup 1.0000x reference)
#include <cuda_runtime.h>

#define NSEQ 2048
#define DMODEL 256
#define NH 8
#define DH 32
#define NB 2
#define BNROWS (NB * NSEQ)   // 4096

// ---------------- packed f32x2 helpers (sm_103a FFMA2 path) ----------------
typedef unsigned long long u64t;

__device__ __forceinline__ u64t pack2(float lo, float hi) {
    u64t r; asm("mov.b64 %0, {%1, %2};" : "=l"(r) : "f"(lo), "f"(hi)); return r;
}
__device__ __forceinline__ void fma2(u64t& acc, u64t a, u64t b) {
    asm("fma.rn.f32x2 %0, %1, %2, %0;" : "+l"(acc) : "l"(a), "l"(b));
}
__device__ __forceinline__ void mul2(u64t& acc, u64t a) {
    asm("mul.rn.f32x2 %0, %1, %0;" : "+l"(acc) : "l"(a));
}
__device__ __forceinline__ void unpack2(u64t v, float& lo, float& hi) {
    asm("mov.b64 {%0, %1}, %2;" : "=f"(lo), "=f"(hi) : "l"(v));
}

// ---------------- device scratch (no allocations allowed) ----------------
__device__ float g_Q[NB * NH * NSEQ * DH];   // (b,h,n,dh)
__device__ float g_K[NB * NH * NSEQ * DH];
__device__ float g_V[NB * NH * NSEQ * DH];
__device__ float g_att[NB * NSEQ * DMODEL];  // (b,n,D) pre-output-proj

// ---------------------------------------------------------------------------
// Kernel 1: QKV projections.  Y = x @ W^T + b, written in (b,h,n,dh) layout.
// f32x2 packed micro-kernel: per k, 2 LDS.128 + 4 packs + 8 FFMA2.
// ---------------------------------------------------------------------------
__global__ __launch_bounds__(256) void qkv_proj_kernel(
    const float* __restrict__ x,
    const float* __restrict__ Wq, const float* __restrict__ bq,
    const float* __restrict__ Wk, const float* __restrict__ bk,
    const float* __restrict__ Wv, const float* __restrict__ bv)
{
    __shared__ float XsT[16][68];   // [k][row]
    __shared__ float WsT[16][68];   // [k][col]

    const float* W; const float* bias; float* dst;
    int z = blockIdx.z;
    if (z == 0)      { W = Wq; bias = bq; dst = g_Q; }
    else if (z == 1) { W = Wk; bias = bk; dst = g_K; }
    else             { W = Wv; bias = bv; dst = g_V; }

    const int i0 = blockIdx.x * 64;
    const int j0 = blockIdx.y * 64;
    const int t  = threadIdx.x;
    const int tx = t & 15, ty = t >> 4;
    const int lr = t >> 2, lk4 = (t & 3) * 4;

    u64t c2[4][2];
    #pragma unroll
    for (int a = 0; a < 4; ++a) { c2[a][0] = 0ull; c2[a][1] = 0ull; }

    for (int kk = 0; kk < DMODEL; kk += 16) {
        float4 xa = *(const float4*)&x[(size_t)(i0 + lr) * DMODEL + kk + lk4];
        float4 wa = *(const float4*)&W[(size_t)(j0 + lr) * DMODEL + kk + lk4];
        XsT[lk4+0][lr] = xa.x; XsT[lk4+1][lr] = xa.y;
        XsT[lk4+2][lr] = xa.z; XsT[lk4+3][lr] = xa.w;
        WsT[lk4+0][lr] = wa.x; WsT[lk4+1][lr] = wa.y;
        WsT[lk4+2][lr] = wa.z; WsT[lk4+3][lr] = wa.w;
        __syncthreads();
        #pragma unroll
        for (int k = 0; k < 16; ++k) {
            float4 a4 = *(const float4*)&XsT[k][ty * 4];
            float4 b4 = *(const float4*)&WsT[k][tx * 4];
            u64t b01 = pack2(b4.x, b4.y);
            u64t b23 = pack2(b4.z, b4.w);
            float av[4] = {a4.x, a4.y, a4.z, a4.w};
            #pragma unroll
            for (int ii = 0; ii < 4; ++ii) {
                u64t aa = pack2(av[ii], av[ii]);
                fma2(c2[ii][0], aa, b01);
                fma2(c2[ii][1], aa, b23);
            }
        }
        __syncthreads();
    }

    #pragma unroll
    for (int ii = 0; ii < 4; ++ii) {
        float cf[4];
        unpack2(c2[ii][0], cf[0], cf[1]);
        unpack2(c2[ii][1], cf[2], cf[3]);
        int i = i0 + ty * 4 + ii;
        int bb = i >> 11;               // batch
        int n  = i & (NSEQ - 1);
        #pragma unroll
        for (int jj = 0; jj < 4; ++jj) {
            int j  = j0 + tx * 4 + jj;
            int hh = j >> 5;
            int dc = j & (DH - 1);
            dst[(((size_t)bb * NH + hh) * NSEQ + n) * DH + dc] = cf[jj] + bias[j];
        }
    }
}

// ---------------------------------------------------------------------------
// Kernel 2: fused flash attention, 2 heads per block, 64q x 64k tiles,
// 4x4 register micro-tiles with packed f32x2 FMA, collapsed edge-bias MLP.
// ---------------------------------------------------------------------------
struct AttnSmem {
    float Qs[2][64][36];   // [head][row][d]
    float Kt[2][32][68];   // [head][d][m]   (K transposed)
    float Vs[64][72];      // [m][head*32+d] (2 heads concat)
    float Ps[2][64][68];   // [head][row][m]
};

__global__ __launch_bounds__(256) void attn_kernel(
    const float* __restrict__ A,
    const float* __restrict__ W1, const float* __restrict__ b1,
    const float* __restrict__ W2, const float* __restrict__ b2)
{
    extern __shared__ char smem_raw[];
    AttnSmem& sm = *reinterpret_cast<AttnSmem*>(smem_raw);

    const int qb = blockIdx.x, hp = blockIdx.y, b = blockIdx.z;
    const int h0 = hp * 2;
    const int q0 = qb * 64;

    const int t  = threadIdx.x;
    const int tx = t & 15, ty = t >> 4;
    const int r0 = ty * 4, c0 = tx * 4;
    const int oh = tx >> 3;            // O head within pair
    const int oc = (tx & 7) * 4;       // O dh col within head

    const float* Qg = g_Q + ((size_t)(b * NH + h0)) * NSEQ * DH;
    const float* Kg = g_K + ((size_t)(b * NH + h0)) * NSEQ * DH;
    const float* Vg = g_V + ((size_t)(b * NH + h0)) * NSEQ * DH;
    const float* Ab = A + (size_t)b * NSEQ * NSEQ;

    // ---- load Q tiles (both heads): 1024 float4, 4 per thread ----
    #pragma unroll
    for (int i = 0; i < 4; ++i) {
        int idx = i * 256 + t;
        int h2 = idx >> 9, rem = idx & 511;
        int rr = rem >> 3, d4 = (rem & 7) * 4;
        float4 v = *(const float4*)&Qg[((size_t)h2 * NSEQ + q0 + rr) * DH + d4];
        *(float4*)&sm.Qs[h2][rr][d4] = v;
    }

    // ---- bias constants (linear collapse valid iff b1 == 0) ----
    float Pc[2], Qc[2], B2[2];
    bool lin;
    {
        float ssum = 0.f;
        #pragma unroll
        for (int k = 0; k < 8; ++k) ssum += fabsf(__ldg(&b1[k]));
        lin = (ssum == 0.f);
        #pragma unroll
        for (int h2 = 0; h2 < 2; ++h2) {
            float p = 0.f, q = 0.f;
            #pragma unroll
            for (int k = 0; k < 8; ++k) {
                float w1k = __ldg(&W1[k]);
                float w2k = __ldg(&W2[(h0 + h2) * NH + k]);
                p = fmaf(w2k, w1k, p);
                q = fmaf(w2k, fabsf(w1k), q);
            }
            Pc[h2] = 0.505f * p;
            Qc[h2] = 0.495f * q;
            B2[h2] = __ldg(&b2[h0 + h2]);
        }
    }
    const float scale = 0.17677669529663687f;  // 1/sqrt(32)

    float mrow[2][4], lrow[2][4];
    u64t acc2[4][2];
    #pragma unroll
    for (int h2 = 0; h2 < 2; ++h2)
        #pragma unroll
        for (int i = 0; i < 4; ++i) { mrow[h2][i] = -3.4e38f; lrow[h2][i] = 0.f; }
    #pragma unroll
    for (int i = 0; i < 4; ++i) { acc2[i][0] = 0ull; acc2[i][1] = 0ull; }

    for (int m0 = 0; m0 < NSEQ; m0 += 64) {
        __syncthreads();  // prev PV done (and Q visible on first iter)

        // ---- load K (transposed) + V (concat) tiles: 4 float4 each ----
        #pragma unroll
        for (int i = 0; i < 4; ++i) {
            int idx = i * 256 + t;
            int h2 = idx >> 9, rem = idx & 511;
            int mm = rem >> 3, d4 = (rem & 7) * 4;
            float4 kv = *(const float4*)&Kg[((size_t)h2 * NSEQ + m0 + mm) * DH + d4];
            sm.Kt[h2][d4 + 0][mm] = kv.x; sm.Kt[h2][d4 + 1][mm] = kv.y;
            sm.Kt[h2][d4 + 2][mm] = kv.z; sm.Kt[h2][d4 + 3][mm] = kv.w;
            float4 vv = *(const float4*)&Vg[((size_t)h2 * NSEQ + m0 + mm) * DH + d4];
            *(float4*)&sm.Vs[mm][h2 * DH + d4] = vv;
        }
        __syncthreads();

        // ---- S = Q K^T : 4x4 micro-tile per head, packed f32x2 ----
        u64t s2[2][4][2];
        #pragma unroll
        for (int h2 = 0; h2 < 2; ++h2)
            #pragma unroll
            for (int i = 0; i < 4; ++i) { s2[h2][i][0] = 0ull; s2[h2][i][1] = 0ull; }

        #pragma unroll 2
        for (int d = 0; d < DH; d += 4) {
            #pragma unroll
            for (int h2 = 0; h2 < 2; ++h2) {
                float4 q4[4];
                #pragma unroll
                for (int i = 0; i < 4; ++i)
                    q4[i] = *(const float4*)&sm.Qs[h2][r0 + i][d];
                #pragma unroll
                for (int dd = 0; dd < 4; ++dd) {
                    float4 kv = *(const float4*)&sm.Kt[h2][d + dd][c0];
                    u64t k01 = pack2(kv.x, kv.y);
                    u64t k23 = pack2(kv.z, kv.w);
                    #pragma unroll
                    for (int i = 0; i < 4; ++i) {
                        float qv = ((const float*)&q4[i])[dd];
                        u64t qq = pack2(qv, qv);
                        fma2(s2[h2][i][0], qq, k01);
                        fma2(s2[h2][i][1], qq, k23);
                    }
                }
            }
        }

        // unpack to scalars for bias + softmax
        float s[2][4][4];
        #pragma unroll
        for (int h2 = 0; h2 < 2; ++h2)
            #pragma unroll
            for (int i = 0; i < 4; ++i) {
                unpack2(s2[h2][i][0], s[h2][i][0], s[h2][i][1]);
                unpack2(s2[h2][i][1], s[h2][i][2], s[h2][i][3]);
            }

        // ---- edge bias (A loads shared by both heads) ----
        #pragma unroll
        for (int i = 0; i < 4; ++i) {
            float4 a4 = *(const float4*)&Ab[(size_t)(q0 + r0 + i) * NSEQ + m0 + c0];
            float af[4] = {a4.x, a4.y, a4.z, a4.w};
            if (lin) {
                #pragma unroll
                for (int h2 = 0; h2 < 2; ++h2)
                    #pragma unroll
                    for (int j = 0; j < 4; ++j) {
                        float bia = fmaf(Pc[h2], af[j], B2[h2]);
                        bia = fmaf(Qc[h2], fabsf(af[j]), bia);
                        s[h2][i][j] = fmaf(s[h2][i][j], scale, bia);
                    }
            } else {
                #pragma unroll
                for (int h2 = 0; h2 < 2; ++h2)
                    #pragma unroll
                    for (int j = 0; j < 4; ++j) {
                        float bia = __ldg(&b2[h0 + h2]);
                        for (int k = 0; k < 8; ++k) {
                            float zz = fmaf(af[j], __ldg(&W1[k]), __ldg(&b1[k]));
                            float hk = fmaxf(zz, 0.01f * zz);
                            bia = fmaf(__ldg(&W2[(h0 + h2) * NH + k]), hk, bia);
                        }
                        s[h2][i][j] = fmaf(s[h2][i][j], scale, bia);
                    }
            }
        }

        // ---- online softmax (16 tx-lanes per row cooperate via shfl) ----
        float alpha2[2][4];
        #pragma unroll
        for (int h2 = 0; h2 < 2; ++h2) {
            #pragma unroll
            for (int i = 0; i < 4; ++i) {
                float tmax = fmaxf(fmaxf(s[h2][i][0], s[h2][i][1]),
                                   fmaxf(s[h2][i][2], s[h2][i][3]));
                tmax = fmaxf(tmax, __shfl_xor_sync(0xffffffffu, tmax, 1));
                tmax = fmaxf(tmax, __shfl_xor_sync(0xffffffffu, tmax, 2));
                tmax = fmaxf(tmax, __shfl_xor_sync(0xffffffffu, tmax, 4));
                tmax = fmaxf(tmax, __shfl_xor_sync(0xffffffffu, tmax, 8));
                float mnew = fmaxf(mrow[h2][i], tmax);
                float al   = __expf(mrow[h2][i] - mnew);
                float tsum = 0.f;
                #pragma unroll
                for (int j = 0; j < 4; ++j) {
                    s[h2][i][j] = __expf(s[h2][i][j] - mnew);
                    tsum += s[h2][i][j];
                }
                tsum += __shfl_xor_sync(0xffffffffu, tsum, 1);
                tsum += __shfl_xor_sync(0xffffffffu, tsum, 2);
                tsum += __shfl_xor_sync(0xffffffffu, tsum, 4);
                tsum += __shfl_xor_sync(0xffffffffu, tsum, 8);
                lrow[h2][i] = lrow[h2][i] * al + tsum;
                mrow[h2][i] = mnew;
                alpha2[h2][i] = al;
            }
        }

        // ---- store P, rescale O accumulators (packed) ----
        #pragma unroll
        for (int h2 = 0; h2 < 2; ++h2)
            #pragma unroll
            for (int i = 0; i < 4; ++i)
                *(float4*)&sm.Ps[h2][r0 + i][c0] =
                    make_float4(s[h2][i][0], s[h2][i][1], s[h2][i][2], s[h2][i][3]);
        #pragma unroll
        for (int i = 0; i < 4; ++i) {
            u64t al2 = pack2(alpha2[oh][i], alpha2[oh][i]);
            mul2(acc2[i][0], al2);
            mul2(acc2[i][1], al2);
        }
        __syncthreads();

        // ---- O += P V  (thread: 4 rows x 4 dh cols of its head, packed) ----
        #pragma unroll 4
        for (int mc = 0; mc < 64; mc += 4) {
            float4 p4[4];
            #pragma unroll
            for (int i = 0; i < 4; ++i)
                p4[i] = *(const float4*)&sm.Ps[oh][r0 + i][mc];
            #pragma unroll
            for (int mm = 0; mm < 4; ++mm) {
                float4 vv = *(const float4*)&sm.Vs[mc + mm][oh * DH + oc];
                u64t v01 = pack2(vv.x, vv.y);
                u64t v23 = pack2(vv.z, vv.w);
                #pragma unroll
                for (int i = 0; i < 4; ++i) {
                    float pv = ((const float*)&p4[i])[mm];
                    u64t pp = pack2(pv, pv);
                    fma2(acc2[i][0], pp, v01);
                    fma2(acc2[i][1], pp, v23);
                }
            }
        }
    }

    // ---- epilogue: normalize, write (b,n,D) ----
    #pragma unroll
    for (int i = 0; i < 4; ++i) {
        float a0, a1, a2, a3;
        unpack2(acc2[i][0], a0, a1);
        unpack2(acc2[i][1], a2, a3);
        float inv = 1.f / lrow[oh][i];
        float* op = g_att + ((size_t)b * NSEQ + q0 + r0 + i) * DMODEL + (h0 + oh) * DH + oc;
        *(float4*)op = make_float4(a0 * inv, a1 * inv, a2 * inv, a3 * inv);
    }
}

// ---------------------------------------------------------------------------
// Kernel 3: output projection.  out = att @ Wo^T + bo.  (packed f32x2)
// ---------------------------------------------------------------------------
__global__ __launch_bounds__(256) void out_proj_kernel(
    const float* __restrict__ Wo, const float* __restrict__ bo,
    float* __restrict__ out)
{
    __shared__ float XsT[16][68];
    __shared__ float WsT[16][68];

    const int i0 = blockIdx.x * 64;
    const int j0 = blockIdx.y * 64;
    const int t  = threadIdx.x;
    const int tx = t & 15, ty = t >> 4;
    const int lr = t >> 2, lk4 = (t & 3) * 4;

    u64t c2[4][2];
    #pragma unroll
    for (int a = 0; a < 4; ++a) { c2[a][0] = 0ull; c2[a][1] = 0ull; }

    for (int kk = 0; kk < DMODEL; kk += 16) {
        float4 xa = *(const float4*)&g_att[(size_t)(i0 + lr) * DMODEL + kk + lk4];
        float4 wa = *(const float4*)&Wo[(size_t)(j0 + lr) * DMODEL + kk + lk4];
        XsT[lk4+0][lr] = xa.x; XsT[lk4+1][lr] = xa.y;
        XsT[lk4+2][lr] = xa.z; XsT[lk4+3][lr] = xa.w;
        WsT[lk4+0][lr] = wa.x; WsT[lk4+1][lr] = wa.y;
        WsT[lk4+2][lr] = wa.z; WsT[lk4+3][lr] = wa.w;
        __syncthreads();
        #pragma unroll
        for (int k = 0; k < 16; ++k) {
            float4 a4 = *(const float4*)&XsT[k][ty * 4];
            float4 b4 = *(const float4*)&WsT[k][tx * 4];
            u64t b01 = pack2(b4.x, b4.y);
            u64t b23 = pack2(b4.z, b4.w);
            float av[4] = {a4.x, a4.y, a4.z, a4.w};
            #pragma unroll
            for (int ii = 0; ii < 4; ++ii) {
                u64t aa = pack2(av[ii], av[ii]);
                fma2(c2[ii][0], aa, b01);
                fma2(c2[ii][1], aa, b23);
            }
        }
        __syncthreads();
    }

    #pragma unroll
    for (int ii = 0; ii < 4; ++ii) {
        float cf[4];
        unpack2(c2[ii][0], cf[0], cf[1]);
        unpack2(c2[ii][1], cf[2], cf[3]);
        int i = i0 + ty * 4 + ii;
        #pragma unroll
        for (int jj = 0; jj < 4; ++jj) {
            int j = j0 + tx * 4 + jj;
            out[(size_t)i * DMODEL + j] = cf[jj] + bo[j];
        }
    }
}

// ---------------------------------------------------------------------------
extern "C" void kernel_launch(void* const* d_in, const int* in_sizes, int n_in,
                              void* d_out, int out_size)
{
    const float* x  = (const float*)d_in[0];
    const float* A  = (const float*)d_in[1];
    const float* Wq = (const float*)d_in[2];
    const float* bq = (const float*)d_in[3];
    const float* Wk = (const float*)d_in[4];
    const float* bk = (const float*)d_in[5];
    const float* Wv = (const float*)d_in[6];
    const float* bv = (const float*)d_in[7];
    const float* Wo = (const float*)d_in[8];
    const float* bo = (const float*)d_in[9];
    const float* W1 = (const float*)d_in[10];
    const float* b1 = (const float*)d_in[11];
    const float* W2 = (const float*)d_in[12];
    const float* b2 = (const float*)d_in[13];
    float* out = (float*)d_out;

    dim3 gProj(BNROWS / 64, DMODEL / 64, 3);
    qkv_proj_kernel<<<gProj, 256>>>(x, Wq, bq, Wk, bk, Wv, bv);

    cudaFuncSetAttribute(attn_kernel, cudaFuncAttributeMaxDynamicSharedMemorySize,
                         (int)sizeof(AttnSmem));
    dim3 gAttn(NSEQ / 64, NH / 2, NB);
    attn_kernel<<<gAttn, 256, sizeof(AttnSmem)>>>(A, W1, b1, W2, b2);

    dim3 gOut(BNROWS / 64, DMODEL / 64);
    out_proj_kernel<<<gOut, 256>>>(Wo, bo, out);
}